// round 1
// baseline (speedup 1.0000x reference)
#include <cuda_runtime.h>
#include <math.h>

// ---------------- problem constants ----------------
#define BB 2
#define SS 1024
#define TT 2048          // BB*SS tokens
#define HH 1024          // hidden
#define NHD 8            // heads
#define NOPE 128
#define QHD 192
#define VD 128
#define QCOLS 1536       // NHD*QHD
#define KVCOLS 2112      // NHD*(NOPE+VD)+64
#define EE 8
#define CAP 2048         // max tokens per expert (<= TT)
#define INTER 1024
#define SHD 1024         // shared expert inter

// ---------------- device scratch (static allocation is allowed) ----------------
__device__ float g_hnorm[TT * HH];
__device__ float g_qfull[TT * QCOLS];
__device__ float g_kv[TT * KVCOLS];
__device__ float g_attn[TT * HH];
__device__ float g_x1[TT * HH];
__device__ float g_h2[TT * HH];
__device__ float g_gu[TT * 2 * SHD];
__device__ float g_act[TT * SHD];
__device__ float g_mid[(size_t)EE * CAP * INTER];
__device__ int   g_cnt[EE];
__device__ int   g_tok[EE * CAP];
__device__ float g_coef[EE * CAP];

// ---------------- RMSNorm ----------------
__global__ void rmsnorm_k(const float* __restrict__ x, const float* __restrict__ w,
                          float* __restrict__ y) {
    int row = blockIdx.x;
    const float* xr = x + (size_t)row * HH;
    float v[4];
    float s = 0.f;
#pragma unroll
    for (int l = 0; l < 4; l++) {
        v[l] = xr[threadIdx.x + l * 256];
        s += v[l] * v[l];
    }
    __shared__ float red[256];
    red[threadIdx.x] = s;
    __syncthreads();
    for (int off = 128; off > 0; off >>= 1) {
        if (threadIdx.x < off) red[threadIdx.x] += red[threadIdx.x + off];
        __syncthreads();
    }
    float scale = rsqrtf(red[0] * (1.0f / HH) + 1e-6f);
    float* yr = y + (size_t)row * HH;
#pragma unroll
    for (int l = 0; l < 4; l++) {
        int i = threadIdx.x + l * 256;
        yr[i] = v[l] * scale * w[i];
    }
}

// ---------------- generic SGEMM:  C[M,N] = A[M,K] @ W[N,K]^T (+ residual) ----------------
// grid: (N/64, M/64), block 256. All dims multiples of 64 (K mult of 16).
template <int EPI>  // 0 = plain, 1 = + residual R[M,N]
__global__ void __launch_bounds__(256) sgemm_k(const float* __restrict__ A,
                                               const float* __restrict__ W,
                                               float* __restrict__ C,
                                               int K, int N,
                                               const float* __restrict__ R) {
    __shared__ __align__(16) float As[16][64];
    __shared__ __align__(16) float Ws[16][64];
    int tid = threadIdx.x;
    int tx = tid & 15, ty = tid >> 4;
    int m0 = blockIdx.y * 64, n0 = blockIdx.x * 64;
    const float* Ab = A + (size_t)m0 * K;
    const float* Wb = W + (size_t)n0 * K;
    float acc[4][4] = {};
    for (int k0 = 0; k0 < K; k0 += 16) {
#pragma unroll
        for (int l = 0; l < 4; l++) {
            int idx = tid + l * 256;
            int r = idx >> 4, c = idx & 15;
            As[c][r] = Ab[r * K + k0 + c];
            Ws[c][r] = Wb[r * K + k0 + c];
        }
        __syncthreads();
#pragma unroll
        for (int kk = 0; kk < 16; kk++) {
            float4 a4 = *(const float4*)(&As[kk][ty * 4]);
            float4 b4 = *(const float4*)(&Ws[kk][tx * 4]);
            float av[4] = {a4.x, a4.y, a4.z, a4.w};
            float bv[4] = {b4.x, b4.y, b4.z, b4.w};
#pragma unroll
            for (int i = 0; i < 4; i++)
#pragma unroll
                for (int j = 0; j < 4; j++)
                    acc[i][j] = fmaf(av[i], bv[j], acc[i][j]);
        }
        __syncthreads();
    }
#pragma unroll
    for (int i = 0; i < 4; i++) {
        int m = m0 + ty * 4 + i;
        float4 o = make_float4(acc[i][0], acc[i][1], acc[i][2], acc[i][3]);
        if (EPI == 1) {
            float4 rr = *(const float4*)&R[(size_t)m * N + n0 + tx * 4];
            o.x += rr.x; o.y += rr.y; o.z += rr.z; o.w += rr.w;
        }
        *(float4*)&C[(size_t)m * N + n0 + tx * 4] = o;
    }
}

// ---------------- flash attention (fp32, causal, d=128, nope-only) ----------------
// grid: (S/64, NHD, BB), block 256, dynamic smem 116480B
__global__ void __launch_bounds__(256) flash_k(const float* __restrict__ qfull,
                                               const float* __restrict__ kv,
                                               float* __restrict__ out) {
    extern __shared__ float sm[];
    float* Qs = sm;                 // [64][129]
    float* Ks = Qs + 64 * 129;      // [64][129]
    float* Vs = Ks + 64 * 129;      // [64][132]
    float* Ps = Vs + 64 * 132;      // [64][65]
    int b = blockIdx.z, h = blockIdx.y, qt = blockIdx.x;
    int tid = threadIdx.x;
    int t0 = b * SS + qt * 64;
    const float scale = rsqrtf((float)QHD);
#pragma unroll
    for (int l = 0; l < 32; l++) {
        int idx = tid + l * 256;
        int r = idx >> 7, d = idx & 127;
        Qs[r * 129 + d] = qfull[(size_t)(t0 + r) * QCOLS + h * QHD + d] * scale;
    }
    int rg = tid >> 4, cgp = tid & 15;
    float m_i[4], l_i[4], acc[4][8];
#pragma unroll
    for (int i = 0; i < 4; i++) {
        m_i[i] = -1e30f; l_i[i] = 0.f;
#pragma unroll
        for (int dd = 0; dd < 8; dd++) acc[i][dd] = 0.f;
    }
    __syncthreads();
    for (int kt = 0; kt <= qt; kt++) {
        int k0g = b * SS + kt * 64;
#pragma unroll
        for (int l = 0; l < 32; l++) {
            int idx = tid + l * 256;
            int r = idx >> 7, d = idx & 127;
            const float* kvrow = kv + (size_t)(k0g + r) * KVCOLS;
            Ks[r * 129 + d] = kvrow[h * NOPE + d];
            Vs[r * 132 + d] = kvrow[NHD * NOPE + h * VD + d];
        }
        __syncthreads();
        float sc[4][4] = {};
        for (int d = 0; d < 128; d++) {
            float qv[4], kvv[4];
#pragma unroll
            for (int i = 0; i < 4; i++) qv[i] = Qs[(rg * 4 + i) * 129 + d];
#pragma unroll
            for (int j = 0; j < 4; j++) kvv[j] = Ks[(cgp * 4 + j) * 129 + d];
#pragma unroll
            for (int i = 0; i < 4; i++)
#pragma unroll
                for (int j = 0; j < 4; j++)
                    sc[i][j] = fmaf(qv[i], kvv[j], sc[i][j]);
        }
        if (kt == qt) {
#pragma unroll
            for (int i = 0; i < 4; i++)
#pragma unroll
                for (int j = 0; j < 4; j++)
                    if (cgp * 4 + j > rg * 4 + i) sc[i][j] = -1e30f;
        }
#pragma unroll
        for (int i = 0; i < 4; i++) {
            float mx = fmaxf(fmaxf(sc[i][0], sc[i][1]), fmaxf(sc[i][2], sc[i][3]));
#pragma unroll
            for (int off = 8; off >= 1; off >>= 1)
                mx = fmaxf(mx, __shfl_xor_sync(0xffffffffu, mx, off));
            float mnew = fmaxf(m_i[i], mx);
            float s = 0.f;
#pragma unroll
            for (int j = 0; j < 4; j++) {
                float p = __expf(sc[i][j] - mnew);
                sc[i][j] = p;
                s += p;
            }
#pragma unroll
            for (int off = 8; off >= 1; off >>= 1)
                s += __shfl_xor_sync(0xffffffffu, s, off);
            float alpha = __expf(m_i[i] - mnew);
            l_i[i] = l_i[i] * alpha + s;
            m_i[i] = mnew;
#pragma unroll
            for (int dd = 0; dd < 8; dd++) acc[i][dd] *= alpha;
#pragma unroll
            for (int j = 0; j < 4; j++)
                Ps[(rg * 4 + i) * 65 + cgp * 4 + j] = sc[i][j];
        }
        __syncthreads();
        for (int c = 0; c < 64; c++) {
            float p[4];
#pragma unroll
            for (int i = 0; i < 4; i++) p[i] = Ps[(rg * 4 + i) * 65 + c];
            float vv[8];
#pragma unroll
            for (int dd = 0; dd < 8; dd++) vv[dd] = Vs[c * 132 + cgp * 8 + dd];
#pragma unroll
            for (int i = 0; i < 4; i++)
#pragma unroll
                for (int dd = 0; dd < 8; dd++)
                    acc[i][dd] = fmaf(p[i], vv[dd], acc[i][dd]);
        }
        __syncthreads();
    }
#pragma unroll
    for (int i = 0; i < 4; i++) {
        float inv = 1.f / l_i[i];
        int trow = t0 + rg * 4 + i;
        float* orow = out + (size_t)trow * HH + h * VD + cgp * 8;
#pragma unroll
        for (int dd = 0; dd < 8; dd++) orow[dd] = acc[i][dd] * inv;
    }
}

// ---------------- router: logits, softmax-top2 (renormalized), bucket tokens ----------------
__global__ void zero_cnt_k() {
    if (threadIdx.x < EE) g_cnt[threadIdx.x] = 0;
}

__global__ void gate_k(const float* __restrict__ h2, const float* __restrict__ gw) {
    int warp = (blockIdx.x * blockDim.x + threadIdx.x) >> 5;
    int lane = threadIdx.x & 31;
    if (warp >= TT) return;
    const float* hr = h2 + (size_t)warp * HH;
    float hv[32];
#pragma unroll
    for (int i = 0; i < 32; i++) hv[i] = hr[lane + i * 32];
    float logits[EE];
#pragma unroll
    for (int e = 0; e < EE; e++) {
        const float* wr = gw + e * HH;
        float s = 0.f;
#pragma unroll
        for (int i = 0; i < 32; i++) s = fmaf(hv[i], wr[lane + i * 32], s);
#pragma unroll
        for (int off = 16; off >= 1; off >>= 1)
            s += __shfl_xor_sync(0xffffffffu, s, off);
        logits[e] = s;
    }
    if (lane == 0) {
        int i0 = 0; float v0 = logits[0];
#pragma unroll
        for (int e = 1; e < EE; e++)
            if (logits[e] > v0) { v0 = logits[e]; i0 = e; }
        int i1 = -1; float v1 = -1e30f;
#pragma unroll
        for (int e = 0; e < EE; e++)
            if (e != i0 && logits[e] > v1) { v1 = logits[e]; i1 = e; }
        // renormalized top-2 of softmax == 2-way softmax over top-2 logits
        float r = __expf(v1 - v0);
        float z = 1.f + r;
        float w0 = 1.f / z, w1 = r / z;
        int p0 = atomicAdd(&g_cnt[i0], 1);
        g_tok[i0 * CAP + p0] = warp; g_coef[i0 * CAP + p0] = w0;
        int p1 = atomicAdd(&g_cnt[i1], 1);
        g_tok[i1 * CAP + p1] = warp; g_coef[i1 * CAP + p1] = w1;
    }
}

// ---------------- expert up: mid = silu(h2[gather] @ w1[e]^T) ----------------
// grid: (CAP/64, INTER/64, EE)
__global__ void __launch_bounds__(256) expert_up_k(const float* __restrict__ h2,
                                                   const float* __restrict__ w1) {
    int e = blockIdx.z;
    int n_e = g_cnt[e];
    int m0 = blockIdx.x * 64;
    if (m0 >= n_e) return;
    __shared__ __align__(16) float As[16][64];
    __shared__ __align__(16) float Ws[16][64];
    __shared__ int toks[64];
    int tid = threadIdx.x;
    if (tid < 64) {
        int i = m0 + tid;
        toks[tid] = (i < n_e) ? g_tok[e * CAP + i] : -1;
    }
    __syncthreads();
    int tx = tid & 15, ty = tid >> 4;
    int n0 = blockIdx.y * 64;
    const float* Wb = w1 + (size_t)e * INTER * HH + (size_t)n0 * HH;
    float acc[4][4] = {};
    for (int k0 = 0; k0 < HH; k0 += 16) {
#pragma unroll
        for (int l = 0; l < 4; l++) {
            int idx = tid + l * 256;
            int r = idx >> 4, c = idx & 15;
            int tk = toks[r];
            As[c][r] = (tk >= 0) ? h2[(size_t)tk * HH + k0 + c] : 0.f;
            Ws[c][r] = Wb[r * HH + k0 + c];
        }
        __syncthreads();
#pragma unroll
        for (int kk = 0; kk < 16; kk++) {
            float4 a4 = *(const float4*)(&As[kk][ty * 4]);
            float4 b4 = *(const float4*)(&Ws[kk][tx * 4]);
            float av[4] = {a4.x, a4.y, a4.z, a4.w};
            float bv[4] = {b4.x, b4.y, b4.z, b4.w};
#pragma unroll
            for (int i = 0; i < 4; i++)
#pragma unroll
                for (int j = 0; j < 4; j++)
                    acc[i][j] = fmaf(av[i], bv[j], acc[i][j]);
        }
        __syncthreads();
    }
#pragma unroll
    for (int i = 0; i < 4; i++) {
        int r = ty * 4 + i;
        if (toks[r] < 0) continue;
        float o[4];
#pragma unroll
        for (int j = 0; j < 4; j++) {
            float xv = acc[i][j];
            o[j] = xv / (1.f + __expf(-xv));
        }
        float* mr = g_mid + ((size_t)e * CAP + m0 + r) * INTER + n0 + tx * 4;
        *(float4*)mr = make_float4(o[0], o[1], o[2], o[3]);
    }
}

// ---------------- expert down: out[tok] += coef * (mid @ w2[e]^T) ----------------
// grid: (CAP/64, HH/64, EE)
__global__ void __launch_bounds__(256) expert_down_k(const float* __restrict__ w2,
                                                     float* __restrict__ out) {
    int e = blockIdx.z;
    int n_e = g_cnt[e];
    int m0 = blockIdx.x * 64;
    if (m0 >= n_e) return;
    __shared__ __align__(16) float As[16][64];
    __shared__ __align__(16) float Ws[16][64];
    __shared__ int toks[64];
    __shared__ float cfs[64];
    int tid = threadIdx.x;
    if (tid < 64) {
        int i = m0 + tid;
        bool ok = (i < n_e);
        toks[tid] = ok ? g_tok[e * CAP + i] : -1;
        cfs[tid] = ok ? g_coef[e * CAP + i] : 0.f;
    }
    __syncthreads();
    int tx = tid & 15, ty = tid >> 4;
    int n0 = blockIdx.y * 64;
    const float* Ab = g_mid + ((size_t)e * CAP + m0) * INTER;
    const float* Wb = w2 + (size_t)e * HH * INTER + (size_t)n0 * INTER;
    float acc[4][4] = {};
    for (int k0 = 0; k0 < INTER; k0 += 16) {
#pragma unroll
        for (int l = 0; l < 4; l++) {
            int idx = tid + l * 256;
            int r = idx >> 4, c = idx & 15;
            As[c][r] = Ab[r * INTER + k0 + c];
            Ws[c][r] = Wb[r * INTER + k0 + c];
        }
        __syncthreads();
#pragma unroll
        for (int kk = 0; kk < 16; kk++) {
            float4 a4 = *(const float4*)(&As[kk][ty * 4]);
            float4 b4 = *(const float4*)(&Ws[kk][tx * 4]);
            float av[4] = {a4.x, a4.y, a4.z, a4.w};
            float bv[4] = {b4.x, b4.y, b4.z, b4.w};
#pragma unroll
            for (int i = 0; i < 4; i++)
#pragma unroll
                for (int j = 0; j < 4; j++)
                    acc[i][j] = fmaf(av[i], bv[j], acc[i][j]);
        }
        __syncthreads();
    }
#pragma unroll
    for (int i = 0; i < 4; i++) {
        int r = ty * 4 + i;
        int tk = toks[r];
        if (tk < 0) continue;
        float cf = cfs[r];
        float* orow = out + (size_t)tk * HH + n0 + tx * 4;
#pragma unroll
        for (int j = 0; j < 4; j++)
            atomicAdd(&orow[j], cf * acc[i][j]);
    }
}

// ---------------- GLU for shared expert ----------------
__global__ void glu_k() {
    int idx = blockIdx.x * blockDim.x + threadIdx.x;
    if (idx >= TT * SHD) return;
    int t = idx >> 10;
    int i = idx & 1023;
    float g = g_gu[(size_t)t * (2 * SHD) + i];
    float u = g_gu[(size_t)t * (2 * SHD) + SHD + i];
    g_act[idx] = g / (1.f + __expf(-g)) * u;
}

// ---------------- launch ----------------
extern "C" void kernel_launch(void* const* d_in, const int* in_sizes, int n_in,
                              void* d_out, int out_size) {
    const float* x   = (const float*)d_in[0];
    // d_in[1] = positions (unused by the reference path)
    const float* ln1 = (const float*)d_in[2];
    const float* ln2 = (const float*)d_in[3];
    const float* Wq  = (const float*)d_in[4];
    const float* Wkv = (const float*)d_in[5];
    const float* Wo  = (const float*)d_in[6];
    const float* gw  = (const float*)d_in[7];
    const float* w1  = (const float*)d_in[8];
    const float* w2  = (const float*)d_in[9];
    const float* sgu = (const float*)d_in[10];
    const float* sdn = (const float*)d_in[11];
    float* out = (float*)d_out;

    void *p_hnorm, *p_qfull, *p_kv, *p_attn, *p_x1, *p_h2, *p_gu, *p_act;
    cudaGetSymbolAddress(&p_hnorm, g_hnorm);
    cudaGetSymbolAddress(&p_qfull, g_qfull);
    cudaGetSymbolAddress(&p_kv,    g_kv);
    cudaGetSymbolAddress(&p_attn,  g_attn);
    cudaGetSymbolAddress(&p_x1,    g_x1);
    cudaGetSymbolAddress(&p_h2,    g_h2);
    cudaGetSymbolAddress(&p_gu,    g_gu);
    cudaGetSymbolAddress(&p_act,   g_act);

    const int SMEM_FLASH = (64 * 129 + 64 * 129 + 64 * 132 + 64 * 65) * 4;  // 116480
    cudaFuncSetAttribute(flash_k, cudaFuncAttributeMaxDynamicSharedMemorySize, SMEM_FLASH);

    // attention block
    rmsnorm_k<<<TT, 256>>>(x, ln1, (float*)p_hnorm);
    {
        dim3 g(QCOLS / 64, TT / 64);
        sgemm_k<0><<<g, 256>>>((const float*)p_hnorm, Wq, (float*)p_qfull, HH, QCOLS, nullptr);
    }
    {
        dim3 g(KVCOLS / 64, TT / 64);
        sgemm_k<0><<<g, 256>>>((const float*)p_hnorm, Wkv, (float*)p_kv, HH, KVCOLS, nullptr);
    }
    {
        dim3 g(SS / 64, NHD, BB);
        flash_k<<<g, 256, SMEM_FLASH>>>((const float*)p_qfull, (const float*)p_kv, (float*)p_attn);
    }
    {
        dim3 g(HH / 64, TT / 64);
        sgemm_k<1><<<g, 256>>>((const float*)p_attn, Wo, (float*)p_x1, HH, HH, x);
    }

    // MoE block
    rmsnorm_k<<<TT, 256>>>((const float*)p_x1, ln2, (float*)p_h2);
    zero_cnt_k<<<1, 32>>>();
    gate_k<<<TT / 8, 256>>>((const float*)p_h2, gw);
    {
        dim3 g((2 * SHD) / 64, TT / 64);
        sgemm_k<0><<<g, 256>>>((const float*)p_h2, sgu, (float*)p_gu, HH, 2 * SHD, nullptr);
    }
    glu_k<<<(TT * SHD) / 256, 256>>>();
    {
        // out = x1 + shared_expert(h2)   (full overwrite of poisoned d_out)
        dim3 g(HH / 64, TT / 64);
        sgemm_k<1><<<g, 256>>>((const float*)p_act, sdn, out, HH, HH, (const float*)p_x1);
    }
    {
        dim3 g(CAP / 64, INTER / 64, EE);
        expert_up_k<<<g, 256>>>((const float*)p_h2, w1);
    }
    {
        dim3 g(CAP / 64, HH / 64, EE);
        expert_down_k<<<g, 256>>>(w2, out);
    }
}

// round 2
// speedup vs baseline: 3.8636x; 3.8636x over previous
#include <cuda_runtime.h>
#include <math.h>
#include <stdint.h>

// ---------------- problem constants ----------------
#define BB 2
#define SS 1024
#define TT 2048          // BB*SS tokens
#define HH 1024          // hidden
#define NHD 8            // heads
#define NOPE 128
#define QHD 192
#define VD 128
#define QCOLS 1536       // NHD*QHD
#define KVC 2048         // NH*(NOPE+VD): rope block of Wkv is unused -> skip it
#define EE 8
#define CAP 2048
#define INTER 1024
#define SHD 1024

// ---------------- device scratch ----------------
__device__ float g_hnorm[TT * HH];
__device__ float g_qfull[TT * QCOLS];
__device__ float g_kv[TT * KVC];
__device__ float g_attn[TT * HH];
__device__ float g_x1[TT * HH];
__device__ float g_h2[TT * HH];
__device__ float g_gu[TT * 2 * SHD];
__device__ float g_act[TT * SHD];
__device__ float g_mid[(size_t)EE * CAP * INTER];
__device__ int   g_cnt[EE];
__device__ int   g_tok[EE * CAP];
__device__ float g_coef[EE * CAP];

// ---------------- small helpers ----------------
__device__ __forceinline__ uint32_t s2u(const void* p) {
    return (uint32_t)__cvta_generic_to_shared(p);
}
__device__ __forceinline__ unsigned f2tf(float f) {
    unsigned r; asm("cvt.rna.tf32.f32 %0, %1;" : "=r"(r) : "f"(f)); return r;
}
__device__ __forceinline__ void mma_tf32(float* c, const unsigned* a, const unsigned* b) {
    asm volatile("mma.sync.aligned.m16n8k8.row.col.f32.tf32.tf32.f32 "
                 "{%0,%1,%2,%3},{%4,%5,%6,%7},{%8,%9},{%0,%1,%2,%3};"
                 : "+f"(c[0]), "+f"(c[1]), "+f"(c[2]), "+f"(c[3])
                 : "r"(a[0]), "r"(a[1]), "r"(a[2]), "r"(a[3]), "r"(b[0]), "r"(b[1]));
}
__device__ __forceinline__ void cpa16(uint32_t d, const void* s) {
    asm volatile("cp.async.cg.shared.global [%0], [%1], 16;" :: "r"(d), "l"(s));
}
__device__ __forceinline__ void cpa_commit() { asm volatile("cp.async.commit_group;"); }
template <int N> __device__ __forceinline__ void cpa_wait() {
    asm volatile("cp.async.wait_group %0;" :: "n"(N));
}

// ---------------- RMSNorm ----------------
__global__ void rmsnorm_k(const float* __restrict__ x, const float* __restrict__ w,
                          float* __restrict__ y) {
    int row = blockIdx.x;
    const float* xr = x + (size_t)row * HH;
    float v[4];
    float s = 0.f;
#pragma unroll
    for (int l = 0; l < 4; l++) {
        v[l] = xr[threadIdx.x + l * 256];
        s += v[l] * v[l];
    }
    __shared__ float red[256];
    red[threadIdx.x] = s;
    __syncthreads();
    for (int off = 128; off > 0; off >>= 1) {
        if (threadIdx.x < off) red[threadIdx.x] += red[threadIdx.x + off];
        __syncthreads();
    }
    float scale = rsqrtf(red[0] * (1.0f / HH) + 1e-6f);
    float* yr = y + (size_t)row * HH;
#pragma unroll
    for (int l = 0; l < 4; l++) {
        int i = threadIdx.x + l * 256;
        yr[i] = v[l] * scale * w[i];
    }
}

// ---------------- tf32 tensor-core GEMM ----------------
// C[M,N] = A[M,K=1024] @ W[N,K=1024]^T.  All row strides hard-coded 1024.
// Tile 128x128x16, 256 threads (8 warps: 4 M x 2 N), warp tile 32x64.
// MODE 0: plain store         MODE 1: + residual R
// MODE 2: expert-up  (gather rows via g_tok, silu, -> g_mid)
// MODE 3: expert-down (A = g_mid rows, atomic scatter *coef into C)
#define SMS 20  // smem row stride in floats (16 data + 4 pad -> conflict-free frags)

template <int MODE>
__global__ void __launch_bounds__(256, 2) mma_gemm_k(
    const float* __restrict__ A, const float* __restrict__ W,
    float* __restrict__ C, int N, const float* __restrict__ R, size_t estride)
{
    __shared__ __align__(16) float sA[2][128 * SMS];
    __shared__ __align__(16) float sW[2][128 * SMS];
    __shared__ int   s_tok[128];
    __shared__ float s_cf[128];

    const int e  = blockIdx.z;
    const int m0 = blockIdx.y * 128;
    const int n0 = blockIdx.x * 128;
    const int tid = threadIdx.x;

    if (MODE == 2 || MODE == 3) {
        int n_e = g_cnt[e];
        if (m0 >= n_e) return;
        if (tid < 128) {
            int i = m0 + tid;
            bool ok = i < n_e;
            s_tok[tid] = ok ? g_tok[e * CAP + i] : -1;
            if (MODE == 3) s_cf[tid] = ok ? g_coef[e * CAP + i] : 0.f;
        }
        __syncthreads();
    }

    const float* Wbase = W + (size_t)e * estride + (size_t)n0 * 1024;
    const float* Arow  = (MODE == 3) ? (g_mid + ((size_t)e * CAP + m0) * 1024)
                                     : (A + (size_t)m0 * 1024);

    uint32_t suA0 = s2u(&sA[0][0]), suA1 = s2u(&sA[1][0]);
    uint32_t suW0 = s2u(&sW[0][0]), suW1 = s2u(&sW[1][0]);

    auto issue = [&](int stage, int it) {
        int k0 = it * 16;
        uint32_t da = stage ? suA1 : suA0;
        uint32_t dw = stage ? suW1 : suW0;
#pragma unroll
        for (int j = 0; j < 2; j++) {
            int q = tid + j * 256;       // float4 index, 512 per tile
            int r = q >> 2, c4 = q & 3;
            const float* srcA;
            if (MODE == 2) {
                int tk = s_tok[r]; if (tk < 0) tk = 0;   // garbage rows masked in epilogue
                srcA = A + (size_t)tk * 1024 + k0 + c4 * 4;
            } else {
                srcA = Arow + (size_t)r * 1024 + k0 + c4 * 4;
            }
            uint32_t off = (uint32_t)(r * SMS + c4 * 4) * 4;
            cpa16(da + off, srcA);
            cpa16(dw + off, Wbase + (size_t)r * 1024 + k0 + c4 * 4);
        }
        cpa_commit();
    };

    const int wid = tid >> 5, lane = tid & 31;
    const int wm = wid & 3, wn = wid >> 2;
    const int lr = lane >> 2, lc = lane & 3;

    float acc[2][8][4] = {};

    issue(0, 0);
    for (int it = 0; it < 64; ++it) {
        int cur = it & 1;
        if (it + 1 < 64) { issue(cur ^ 1, it + 1); cpa_wait<1>(); }
        else             { cpa_wait<0>(); }
        __syncthreads();
        const float* As = sA[cur];
        const float* Ws = sW[cur];
#pragma unroll
        for (int ks = 0; ks < 16; ks += 8) {
            unsigned af[2][4];
#pragma unroll
            for (int mt = 0; mt < 2; mt++) {
                int row = wm * 32 + mt * 16 + lr;
                int k = ks + lc;
                af[mt][0] = f2tf(As[row * SMS + k]);
                af[mt][1] = f2tf(As[(row + 8) * SMS + k]);
                af[mt][2] = f2tf(As[row * SMS + k + 4]);
                af[mt][3] = f2tf(As[(row + 8) * SMS + k + 4]);
            }
#pragma unroll
            for (int nt = 0; nt < 8; nt++) {
                unsigned bf[2];
                int n = wn * 64 + nt * 8 + lr;
                int k = ks + lc;
                bf[0] = f2tf(Ws[n * SMS + k]);
                bf[1] = f2tf(Ws[n * SMS + k + 4]);
                mma_tf32(acc[0][nt], af[0], bf);
                mma_tf32(acc[1][nt], af[1], bf);
            }
        }
        __syncthreads();
    }

    // epilogue
#pragma unroll
    for (int mt = 0; mt < 2; mt++)
#pragma unroll
    for (int i = 0; i < 2; i++) {
        int rloc = wm * 32 + mt * 16 + lr + i * 8;
#pragma unroll
        for (int nt = 0; nt < 8; nt++) {
            float v0 = acc[mt][nt][2 * i], v1 = acc[mt][nt][2 * i + 1];
            int col = n0 + wn * 64 + nt * 8 + 2 * lc;
            if (MODE == 0) {
                *(float2*)&C[(size_t)(m0 + rloc) * N + col] = make_float2(v0, v1);
            } else if (MODE == 1) {
                float2 rr = *(const float2*)&R[(size_t)(m0 + rloc) * N + col];
                *(float2*)&C[(size_t)(m0 + rloc) * N + col] = make_float2(v0 + rr.x, v1 + rr.y);
            } else if (MODE == 2) {
                if (s_tok[rloc] >= 0) {
                    float o0 = v0 / (1.f + __expf(-v0));
                    float o1 = v1 / (1.f + __expf(-v1));
                    *(float2*)&g_mid[((size_t)e * CAP + m0 + rloc) * 1024 + col] =
                        make_float2(o0, o1);
                }
            } else {
                int tk = s_tok[rloc];
                if (tk >= 0) {
                    float cf = s_cf[rloc];
                    atomicAdd(&C[(size_t)tk * 1024 + col],     cf * v0);
                    atomicAdd(&C[(size_t)tk * 1024 + col + 1], cf * v1);
                }
            }
        }
    }
}

// ---------------- flash attention (fp32, causal, d=128, nope-only) ----------------
__global__ void __launch_bounds__(256) flash_k(const float* __restrict__ qfull,
                                               const float* __restrict__ kv,
                                               float* __restrict__ out) {
    extern __shared__ float sm[];
    float* Qs = sm;                 // [64][129]
    float* Ks = Qs + 64 * 129;      // [64][129]
    float* Vs = Ks + 64 * 129;      // [64][132]
    float* Ps = Vs + 64 * 132;      // [64][65]
    int b = blockIdx.z, h = blockIdx.y, qt = blockIdx.x;
    int tid = threadIdx.x;
    int t0 = b * SS + qt * 64;
    const float scale = rsqrtf((float)QHD);
#pragma unroll
    for (int l = 0; l < 32; l++) {
        int idx = tid + l * 256;
        int r = idx >> 7, d = idx & 127;
        Qs[r * 129 + d] = qfull[(size_t)(t0 + r) * QCOLS + h * QHD + d] * scale;
    }
    int rg = tid >> 4, cgp = tid & 15;
    float m_i[4], l_i[4], acc[4][8];
#pragma unroll
    for (int i = 0; i < 4; i++) {
        m_i[i] = -1e30f; l_i[i] = 0.f;
#pragma unroll
        for (int dd = 0; dd < 8; dd++) acc[i][dd] = 0.f;
    }
    __syncthreads();
    for (int kt = 0; kt <= qt; kt++) {
        int k0g = b * SS + kt * 64;
#pragma unroll
        for (int l = 0; l < 32; l++) {
            int idx = tid + l * 256;
            int r = idx >> 7, d = idx & 127;
            const float* kvrow = kv + (size_t)(k0g + r) * KVC;
            Ks[r * 129 + d] = kvrow[h * NOPE + d];
            Vs[r * 132 + d] = kvrow[NHD * NOPE + h * VD + d];
        }
        __syncthreads();
        float sc[4][4] = {};
        for (int d = 0; d < 128; d++) {
            float qv[4], kvv[4];
#pragma unroll
            for (int i = 0; i < 4; i++) qv[i] = Qs[(rg * 4 + i) * 129 + d];
#pragma unroll
            for (int j = 0; j < 4; j++) kvv[j] = Ks[(cgp * 4 + j) * 129 + d];
#pragma unroll
            for (int i = 0; i < 4; i++)
#pragma unroll
                for (int j = 0; j < 4; j++)
                    sc[i][j] = fmaf(qv[i], kvv[j], sc[i][j]);
        }
        if (kt == qt) {
#pragma unroll
            for (int i = 0; i < 4; i++)
#pragma unroll
                for (int j = 0; j < 4; j++)
                    if (cgp * 4 + j > rg * 4 + i) sc[i][j] = -1e30f;
        }
#pragma unroll
        for (int i = 0; i < 4; i++) {
            float mx = fmaxf(fmaxf(sc[i][0], sc[i][1]), fmaxf(sc[i][2], sc[i][3]));
#pragma unroll
            for (int off = 8; off >= 1; off >>= 1)
                mx = fmaxf(mx, __shfl_xor_sync(0xffffffffu, mx, off));
            float mnew = fmaxf(m_i[i], mx);
            float s = 0.f;
#pragma unroll
            for (int j = 0; j < 4; j++) {
                float p = __expf(sc[i][j] - mnew);
                sc[i][j] = p;
                s += p;
            }
#pragma unroll
            for (int off = 8; off >= 1; off >>= 1)
                s += __shfl_xor_sync(0xffffffffu, s, off);
            float alpha = __expf(m_i[i] - mnew);
            l_i[i] = l_i[i] * alpha + s;
            m_i[i] = mnew;
#pragma unroll
            for (int dd = 0; dd < 8; dd++) acc[i][dd] *= alpha;
#pragma unroll
            for (int j = 0; j < 4; j++)
                Ps[(rg * 4 + i) * 65 + cgp * 4 + j] = sc[i][j];
        }
        __syncthreads();
        for (int c = 0; c < 64; c++) {
            float p[4];
#pragma unroll
            for (int i = 0; i < 4; i++) p[i] = Ps[(rg * 4 + i) * 65 + c];
            float vv[8];
#pragma unroll
            for (int dd = 0; dd < 8; dd++) vv[dd] = Vs[c * 132 + cgp * 8 + dd];
#pragma unroll
            for (int i = 0; i < 4; i++)
#pragma unroll
                for (int dd = 0; dd < 8; dd++)
                    acc[i][dd] = fmaf(p[i], vv[dd], acc[i][dd]);
        }
        __syncthreads();
    }
#pragma unroll
    for (int i = 0; i < 4; i++) {
        float inv = 1.f / l_i[i];
        int trow = t0 + rg * 4 + i;
        float* orow = out + (size_t)trow * HH + h * VD + cgp * 8;
#pragma unroll
        for (int dd = 0; dd < 8; dd++) orow[dd] = acc[i][dd] * inv;
    }
}

// ---------------- router ----------------
__global__ void zero_cnt_k() {
    if (threadIdx.x < EE) g_cnt[threadIdx.x] = 0;
}

__global__ void gate_k(const float* __restrict__ h2, const float* __restrict__ gw) {
    int warp = (blockIdx.x * blockDim.x + threadIdx.x) >> 5;
    int lane = threadIdx.x & 31;
    if (warp >= TT) return;
    const float* hr = h2 + (size_t)warp * HH;
    float hv[32];
#pragma unroll
    for (int i = 0; i < 32; i++) hv[i] = hr[lane + i * 32];
    float logits[EE];
#pragma unroll
    for (int e = 0; e < EE; e++) {
        const float* wr = gw + e * HH;
        float s = 0.f;
#pragma unroll
        for (int i = 0; i < 32; i++) s = fmaf(hv[i], wr[lane + i * 32], s);
#pragma unroll
        for (int off = 16; off >= 1; off >>= 1)
            s += __shfl_xor_sync(0xffffffffu, s, off);
        logits[e] = s;
    }
    if (lane == 0) {
        int i0 = 0; float v0 = logits[0];
#pragma unroll
        for (int e = 1; e < EE; e++)
            if (logits[e] > v0) { v0 = logits[e]; i0 = e; }
        int i1 = -1; float v1 = -1e30f;
#pragma unroll
        for (int e = 0; e < EE; e++)
            if (e != i0 && logits[e] > v1) { v1 = logits[e]; i1 = e; }
        float r = __expf(v1 - v0);
        float z = 1.f + r;
        float w0 = 1.f / z, w1 = r / z;
        int p0 = atomicAdd(&g_cnt[i0], 1);
        g_tok[i0 * CAP + p0] = warp; g_coef[i0 * CAP + p0] = w0;
        int p1 = atomicAdd(&g_cnt[i1], 1);
        g_tok[i1 * CAP + p1] = warp; g_coef[i1 * CAP + p1] = w1;
    }
}

// ---------------- GLU for shared expert ----------------
__global__ void glu_k() {
    int idx = blockIdx.x * blockDim.x + threadIdx.x;
    if (idx >= TT * SHD) return;
    int t = idx >> 10;
    int i = idx & 1023;
    float g = g_gu[(size_t)t * (2 * SHD) + i];
    float u = g_gu[(size_t)t * (2 * SHD) + SHD + i];
    g_act[idx] = g / (1.f + __expf(-g)) * u;
}

// ---------------- launch ----------------
extern "C" void kernel_launch(void* const* d_in, const int* in_sizes, int n_in,
                              void* d_out, int out_size) {
    const float* x   = (const float*)d_in[0];
    const float* ln1 = (const float*)d_in[2];
    const float* ln2 = (const float*)d_in[3];
    const float* Wq  = (const float*)d_in[4];
    const float* Wkv = (const float*)d_in[5];
    const float* Wo  = (const float*)d_in[6];
    const float* gw  = (const float*)d_in[7];
    const float* w1  = (const float*)d_in[8];
    const float* w2  = (const float*)d_in[9];
    const float* sgu = (const float*)d_in[10];
    const float* sdn = (const float*)d_in[11];
    float* out = (float*)d_out;

    void *p_hnorm, *p_qfull, *p_kv, *p_attn, *p_x1, *p_h2, *p_gu, *p_act;
    cudaGetSymbolAddress(&p_hnorm, g_hnorm);
    cudaGetSymbolAddress(&p_qfull, g_qfull);
    cudaGetSymbolAddress(&p_kv,    g_kv);
    cudaGetSymbolAddress(&p_attn,  g_attn);
    cudaGetSymbolAddress(&p_x1,    g_x1);
    cudaGetSymbolAddress(&p_h2,    g_h2);
    cudaGetSymbolAddress(&p_gu,    g_gu);
    cudaGetSymbolAddress(&p_act,   g_act);

    const int SMEM_FLASH = (64 * 129 + 64 * 129 + 64 * 132 + 64 * 65) * 4;
    cudaFuncSetAttribute(flash_k, cudaFuncAttributeMaxDynamicSharedMemorySize, SMEM_FLASH);

    // attention block
    rmsnorm_k<<<TT, 256>>>(x, ln1, (float*)p_hnorm);
    mma_gemm_k<0><<<dim3(QCOLS / 128, TT / 128), 256>>>(
        (const float*)p_hnorm, Wq, (float*)p_qfull, QCOLS, nullptr, 0);
    mma_gemm_k<0><<<dim3(KVC / 128, TT / 128), 256>>>(
        (const float*)p_hnorm, Wkv, (float*)p_kv, KVC, nullptr, 0);
    flash_k<<<dim3(SS / 64, NHD, BB), 256, SMEM_FLASH>>>(
        (const float*)p_qfull, (const float*)p_kv, (float*)p_attn);
    mma_gemm_k<1><<<dim3(HH / 128, TT / 128), 256>>>(
        (const float*)p_attn, Wo, (float*)p_x1, HH, x, 0);

    // MoE block
    rmsnorm_k<<<TT, 256>>>((const float*)p_x1, ln2, (float*)p_h2);
    zero_cnt_k<<<1, 32>>>();
    gate_k<<<TT / 8, 256>>>((const float*)p_h2, gw);
    mma_gemm_k<0><<<dim3((2 * SHD) / 128, TT / 128), 256>>>(
        (const float*)p_h2, sgu, (float*)p_gu, 2 * SHD, nullptr, 0);
    glu_k<<<(TT * SHD) / 256, 256>>>();
    // out = x1 + shared_expert  (full overwrite of poisoned d_out)
    mma_gemm_k<1><<<dim3(HH / 128, TT / 128), 256>>>(
        (const float*)p_act, sdn, out, HH, (const float*)p_x1, 0);
    // routed experts
    mma_gemm_k<2><<<dim3(INTER / 128, CAP / 128, EE), 256>>>(
        (const float*)p_h2, w1, nullptr, INTER, nullptr, (size_t)INTER * HH);
    mma_gemm_k<3><<<dim3(HH / 128, CAP / 128, EE), 256>>>(
        nullptr, w2, out, HH, nullptr, (size_t)HH * INTER);
}

// round 3
// speedup vs baseline: 4.8540x; 1.2564x over previous
#include <cuda_runtime.h>
#include <math.h>
#include <stdint.h>

// ---------------- problem constants ----------------
#define BB 2
#define SS 1024
#define TT 2048
#define HH 1024
#define NHD 8
#define NOPE 128
#define QHD 192
#define VD 128
#define QCOLS 1536
#define KVC 2048          // rope block of Wkv unused -> skip
#define EE 8
#define CAP 2048
#define INTER 1024
#define SHD 1024

// ---------------- device scratch ----------------
__device__ float g_hnorm[TT * HH];
__device__ float g_qfull[TT * QCOLS];
__device__ float g_kv[TT * KVC];
__device__ float g_attn[TT * HH];
__device__ float g_x1[TT * HH];
__device__ float g_h2[TT * HH];
__device__ float g_gu[TT * 2 * SHD];
__device__ float g_act[TT * SHD];
__device__ float g_mid[(size_t)EE * CAP * INTER];
__device__ int   g_cnt[EE];
__device__ int   g_tok[EE * CAP];
__device__ float g_coef[EE * CAP];

// ---------------- helpers ----------------
__device__ __forceinline__ uint32_t s2u(const void* p) {
    return (uint32_t)__cvta_generic_to_shared(p);
}
__device__ __forceinline__ unsigned f2tf(float f) {
    unsigned r; asm("cvt.rna.tf32.f32 %0, %1;" : "=r"(r) : "f"(f)); return r;
}
__device__ __forceinline__ void mma_tf32(float* c, const unsigned* a, const unsigned* b) {
    asm volatile("mma.sync.aligned.m16n8k8.row.col.f32.tf32.tf32.f32 "
                 "{%0,%1,%2,%3},{%4,%5,%6,%7},{%8,%9},{%0,%1,%2,%3};"
                 : "+f"(c[0]), "+f"(c[1]), "+f"(c[2]), "+f"(c[3])
                 : "r"(a[0]), "r"(a[1]), "r"(a[2]), "r"(a[3]), "r"(b[0]), "r"(b[1]));
}
__device__ __forceinline__ void cpa16(uint32_t d, const void* s) {
    asm volatile("cp.async.cg.shared.global [%0], [%1], 16;" :: "r"(d), "l"(s));
}
__device__ __forceinline__ void cpa_commit() { asm volatile("cp.async.commit_group;"); }
template <int N> __device__ __forceinline__ void cpa_wait() {
    asm volatile("cp.async.wait_group %0;" :: "n"(N));
}

// ---------------- RMSNorm ----------------
__global__ void rmsnorm_k(const float* __restrict__ x, const float* __restrict__ w,
                          float* __restrict__ y) {
    int row = blockIdx.x;
    const float* xr = x + (size_t)row * HH;
    float v[4];
    float s = 0.f;
#pragma unroll
    for (int l = 0; l < 4; l++) {
        v[l] = xr[threadIdx.x + l * 256];
        s += v[l] * v[l];
    }
    __shared__ float red[256];
    red[threadIdx.x] = s;
    __syncthreads();
    for (int off = 128; off > 0; off >>= 1) {
        if (threadIdx.x < off) red[threadIdx.x] += red[threadIdx.x + off];
        __syncthreads();
    }
    float scale = rsqrtf(red[0] * (1.0f / HH) + 1e-6f);
    float* yr = y + (size_t)row * HH;
#pragma unroll
    for (int l = 0; l < 4; l++) {
        int i = threadIdx.x + l * 256;
        yr[i] = v[l] * scale * w[i];
    }
}

// ---------------- tf32 GEMM, 3-stage cp.async pipeline ----------------
// C[M,N] = A[M,1024] @ W[N,1024]^T. Tile 128x128x16, 256 thr, warp 32x64.
// MODE 0 plain / 1 +residual / 2 expert-up silu->g_mid / 3 expert-down atomic
#define SMS 20
#define GTILE (128 * SMS)

template <int MODE>
__global__ void __launch_bounds__(256, 2) mma_gemm_k(
    const float* __restrict__ A, const float* __restrict__ W,
    float* __restrict__ C, int N, const float* __restrict__ R, size_t estride)
{
    extern __shared__ __align__(16) float dyn[];
    float* sA = dyn;                // [3][GTILE]
    float* sW = dyn + 3 * GTILE;    // [3][GTILE]
    __shared__ int   s_tok[128];
    __shared__ float s_cf[128];

    const int e  = blockIdx.z;
    const int m0 = blockIdx.y * 128;
    const int n0 = blockIdx.x * 128;
    const int tid = threadIdx.x;

    if (MODE == 2 || MODE == 3) {
        int n_e = g_cnt[e];
        if (m0 >= n_e) return;
        if (tid < 128) {
            int i = m0 + tid;
            bool ok = i < n_e;
            s_tok[tid] = ok ? g_tok[e * CAP + i] : -1;
            if (MODE == 3) s_cf[tid] = ok ? g_coef[e * CAP + i] : 0.f;
        }
        __syncthreads();
    }

    const float* Wbase = W + (size_t)e * estride + (size_t)n0 * 1024;
    const float* Arow  = (MODE == 3) ? (g_mid + ((size_t)e * CAP + m0) * 1024)
                                     : (A + (size_t)m0 * 1024);

    auto issue = [&](int stage, int it) {
        int k0 = it * 16;
        uint32_t da = s2u(sA + stage * GTILE);
        uint32_t dw = s2u(sW + stage * GTILE);
#pragma unroll
        for (int j = 0; j < 2; j++) {
            int q = tid + j * 256;
            int r = q >> 2, c4 = q & 3;
            const float* srcA;
            if (MODE == 2) {
                int tk = s_tok[r]; if (tk < 0) tk = 0;
                srcA = A + (size_t)tk * 1024 + k0 + c4 * 4;
            } else {
                srcA = Arow + (size_t)r * 1024 + k0 + c4 * 4;
            }
            uint32_t off = (uint32_t)(r * SMS + c4 * 4) * 4;
            cpa16(da + off, srcA);
            cpa16(dw + off, Wbase + (size_t)r * 1024 + k0 + c4 * 4);
        }
        cpa_commit();
    };

    const int wid = tid >> 5, lane = tid & 31;
    const int wm = wid & 3, wn = wid >> 2;
    const int lr = lane >> 2, lc = lane & 3;

    float acc[2][8][4] = {};

    issue(0, 0);
    issue(1, 1);
    for (int it = 0; it < 64; ++it) {
        int cur = it % 3;
        cpa_wait<1>();
        __syncthreads();
        if (it + 2 < 64) issue((it + 2) % 3, it + 2);
        const float* As = sA + cur * GTILE;
        const float* Ws = sW + cur * GTILE;
#pragma unroll
        for (int ks = 0; ks < 16; ks += 8) {
            unsigned af[2][4];
#pragma unroll
            for (int mt = 0; mt < 2; mt++) {
                int row = wm * 32 + mt * 16 + lr;
                int k = ks + lc;
                af[mt][0] = f2tf(As[row * SMS + k]);
                af[mt][1] = f2tf(As[(row + 8) * SMS + k]);
                af[mt][2] = f2tf(As[row * SMS + k + 4]);
                af[mt][3] = f2tf(As[(row + 8) * SMS + k + 4]);
            }
#pragma unroll
            for (int nt = 0; nt < 8; nt++) {
                unsigned bf[2];
                int n = wn * 64 + nt * 8 + lr;
                int k = ks + lc;
                bf[0] = f2tf(Ws[n * SMS + k]);
                bf[1] = f2tf(Ws[n * SMS + k + 4]);
                mma_tf32(acc[0][nt], af[0], bf);
                mma_tf32(acc[1][nt], af[1], bf);
            }
        }
    }

#pragma unroll
    for (int mt = 0; mt < 2; mt++)
#pragma unroll
    for (int i = 0; i < 2; i++) {
        int rloc = wm * 32 + mt * 16 + lr + i * 8;
#pragma unroll
        for (int nt = 0; nt < 8; nt++) {
            float v0 = acc[mt][nt][2 * i], v1 = acc[mt][nt][2 * i + 1];
            int col = n0 + wn * 64 + nt * 8 + 2 * lc;
            if (MODE == 0) {
                *(float2*)&C[(size_t)(m0 + rloc) * N + col] = make_float2(v0, v1);
            } else if (MODE == 1) {
                float2 rr = *(const float2*)&R[(size_t)(m0 + rloc) * N + col];
                *(float2*)&C[(size_t)(m0 + rloc) * N + col] = make_float2(v0 + rr.x, v1 + rr.y);
            } else if (MODE == 2) {
                if (s_tok[rloc] >= 0) {
                    float o0 = v0 / (1.f + __expf(-v0));
                    float o1 = v1 / (1.f + __expf(-v1));
                    *(float2*)&g_mid[((size_t)e * CAP + m0 + rloc) * 1024 + col] =
                        make_float2(o0, o1);
                }
            } else {
                int tk = s_tok[rloc];
                if (tk >= 0) {
                    float cf = s_cf[rloc];
                    atomicAdd(&C[(size_t)tk * 1024 + col],     cf * v0);
                    atomicAdd(&C[(size_t)tk * 1024 + col + 1], cf * v1);
                }
            }
        }
    }
}

// ---------------- tensor-core flash attention ----------------
// 64 q-rows per block, 4 warps (m16 each), K/V tiles of 64 double-buffered.
#define FQS 132   // Qs/Ks row stride (floats)
#define FVS 136   // Vs row stride
#define FPS 68    // Ps row stride
#define FL_SMEM ((64 * FQS + 2 * 64 * FQS + 2 * 64 * FVS + 64 * FPS) * 4)

__global__ void __launch_bounds__(128) flashmma_k(const float* __restrict__ qfull,
                                                  const float* __restrict__ kv,
                                                  float* __restrict__ out) {
    extern __shared__ __align__(16) float sm[];
    float* Qs = sm;                      // [64][FQS]
    float* Ks = Qs + 64 * FQS;           // [2][64][FQS]
    float* Vs = Ks + 2 * 64 * FQS;       // [2][64][FVS]
    float* Ps = Vs + 2 * 64 * FVS;       // [64][FPS]

    const int b = blockIdx.z, h = blockIdx.y, qt = blockIdx.x;
    const int tid = threadIdx.x, wid = tid >> 5, lane = tid & 31;
    const int lr = lane >> 2, lc = lane & 3;
    const int t0 = b * SS + qt * 64;
    const float scale = rsqrtf((float)QHD);

    // Q load (part of cp.async group 0)
    {
        uint32_t qb = s2u(Qs);
#pragma unroll
        for (int j = 0; j < 16; j++) {
            int q = tid + j * 128;
            int r = q >> 5, c4 = q & 31;
            cpa16(qb + (uint32_t)(r * FQS + c4 * 4) * 4,
                  qfull + (size_t)(t0 + r) * QCOLS + h * QHD + c4 * 4);
        }
    }
    auto issue_kv = [&](int stage, int kt) {
        int k0g = b * SS + kt * 64;
        uint32_t kb = s2u(Ks + stage * 64 * FQS);
        uint32_t vb = s2u(Vs + stage * 64 * FVS);
#pragma unroll
        for (int j = 0; j < 16; j++) {
            int q = tid + j * 128;
            int r = q >> 5, c4 = q & 31;
            const float* kvrow = kv + (size_t)(k0g + r) * KVC;
            cpa16(kb + (uint32_t)(r * FQS + c4 * 4) * 4, kvrow + h * NOPE + c4 * 4);
            cpa16(vb + (uint32_t)(r * FVS + c4 * 4) * 4, kvrow + NHD * NOPE + h * VD + c4 * 4);
        }
        cpa_commit();
    };
    issue_kv(0, 0);

    float m0r = -1e30f, m1r = -1e30f, l0 = 0.f, l1 = 0.f;
    float o[16][4];
#pragma unroll
    for (int nt = 0; nt < 16; nt++)
#pragma unroll
        for (int j = 0; j < 4; j++) o[nt][j] = 0.f;

    const int qrow = wid * 16 + lr;

    for (int kt = 0; kt <= qt; kt++) {
        int cur = kt & 1;
        cpa_wait<0>();
        __syncthreads();
        if (kt < qt) issue_kv(cur ^ 1, kt + 1);
        const float* Kb = Ks + cur * 64 * FQS;
        const float* Vb = Vs + cur * 64 * FVS;

        // S = Q K^T  (16 x 64 per warp)
        float sc[8][4] = {};
#pragma unroll
        for (int kk = 0; kk < 128; kk += 8) {
            unsigned a[4];
            a[0] = f2tf(Qs[qrow * FQS + kk + lc]);
            a[1] = f2tf(Qs[(qrow + 8) * FQS + kk + lc]);
            a[2] = f2tf(Qs[qrow * FQS + kk + lc + 4]);
            a[3] = f2tf(Qs[(qrow + 8) * FQS + kk + lc + 4]);
#pragma unroll
            for (int nt = 0; nt < 8; nt++) {
                unsigned bb[2];
                bb[0] = f2tf(Kb[(nt * 8 + lr) * FQS + kk + lc]);
                bb[1] = f2tf(Kb[(nt * 8 + lr) * FQS + kk + lc + 4]);
                mma_tf32(sc[nt], a, bb);
            }
        }
#pragma unroll
        for (int nt = 0; nt < 8; nt++)
#pragma unroll
            for (int j = 0; j < 4; j++) sc[nt][j] *= scale;
        if (kt == qt) {
#pragma unroll
            for (int nt = 0; nt < 8; nt++)
#pragma unroll
                for (int j = 0; j < 4; j++) {
                    int colg = kt * 64 + nt * 8 + 2 * lc + (j & 1);
                    int rowg = qt * 64 + qrow + (j >> 1) * 8;
                    if (colg > rowg) sc[nt][j] = -1e30f;
                }
        }
        // row softmax (rows qrow, qrow+8)
        float mx0 = -1e30f, mx1 = -1e30f;
#pragma unroll
        for (int nt = 0; nt < 8; nt++) {
            mx0 = fmaxf(mx0, fmaxf(sc[nt][0], sc[nt][1]));
            mx1 = fmaxf(mx1, fmaxf(sc[nt][2], sc[nt][3]));
        }
        mx0 = fmaxf(mx0, __shfl_xor_sync(0xffffffffu, mx0, 1));
        mx0 = fmaxf(mx0, __shfl_xor_sync(0xffffffffu, mx0, 2));
        mx1 = fmaxf(mx1, __shfl_xor_sync(0xffffffffu, mx1, 1));
        mx1 = fmaxf(mx1, __shfl_xor_sync(0xffffffffu, mx1, 2));
        float mn0 = fmaxf(m0r, mx0), mn1 = fmaxf(m1r, mx1);
        float a0 = __expf(m0r - mn0), a1 = __expf(m1r - mn1);
        float s0 = 0.f, s1 = 0.f;
#pragma unroll
        for (int nt = 0; nt < 8; nt++) {
            sc[nt][0] = __expf(sc[nt][0] - mn0);
            sc[nt][1] = __expf(sc[nt][1] - mn0);
            sc[nt][2] = __expf(sc[nt][2] - mn1);
            sc[nt][3] = __expf(sc[nt][3] - mn1);
            s0 += sc[nt][0] + sc[nt][1];
            s1 += sc[nt][2] + sc[nt][3];
        }
        s0 += __shfl_xor_sync(0xffffffffu, s0, 1);
        s0 += __shfl_xor_sync(0xffffffffu, s0, 2);
        s1 += __shfl_xor_sync(0xffffffffu, s1, 1);
        s1 += __shfl_xor_sync(0xffffffffu, s1, 2);
        l0 = l0 * a0 + s0; l1 = l1 * a1 + s1;
        m0r = mn0; m1r = mn1;
#pragma unroll
        for (int nt = 0; nt < 16; nt++) {
            o[nt][0] *= a0; o[nt][1] *= a0;
            o[nt][2] *= a1; o[nt][3] *= a1;
        }
        // P -> smem (same warp only)
#pragma unroll
        for (int nt = 0; nt < 8; nt++) {
            *(float2*)&Ps[qrow * FPS + nt * 8 + 2 * lc]       = make_float2(sc[nt][0], sc[nt][1]);
            *(float2*)&Ps[(qrow + 8) * FPS + nt * 8 + 2 * lc] = make_float2(sc[nt][2], sc[nt][3]);
        }
        __syncwarp();
        // O += P V   (k = 64 keys, n = 128 dims)
#pragma unroll
        for (int kk = 0; kk < 64; kk += 8) {
            unsigned a[4];
            a[0] = f2tf(Ps[qrow * FPS + kk + lc]);
            a[1] = f2tf(Ps[(qrow + 8) * FPS + kk + lc]);
            a[2] = f2tf(Ps[qrow * FPS + kk + lc + 4]);
            a[3] = f2tf(Ps[(qrow + 8) * FPS + kk + lc + 4]);
#pragma unroll
            for (int nt = 0; nt < 16; nt++) {
                unsigned bb[2];
                bb[0] = f2tf(Vb[(kk + lc) * FVS + nt * 8 + lr]);
                bb[1] = f2tf(Vb[(kk + lc + 4) * FVS + nt * 8 + lr]);
                mma_tf32(o[nt], a, bb);
            }
        }
        __syncwarp();
    }

    float inv0 = 1.f / l0, inv1 = 1.f / l1;
    int r0 = t0 + qrow, r1 = r0 + 8;
#pragma unroll
    for (int nt = 0; nt < 16; nt++) {
        int col = h * VD + nt * 8 + 2 * lc;
        *(float2*)&out[(size_t)r0 * HH + col] = make_float2(o[nt][0] * inv0, o[nt][1] * inv0);
        *(float2*)&out[(size_t)r1 * HH + col] = make_float2(o[nt][2] * inv1, o[nt][3] * inv1);
    }
}

// ---------------- router ----------------
__global__ void zero_cnt_k() {
    if (threadIdx.x < EE) g_cnt[threadIdx.x] = 0;
}

__global__ void gate_k(const float* __restrict__ h2, const float* __restrict__ gw) {
    int warp = (blockIdx.x * blockDim.x + threadIdx.x) >> 5;
    int lane = threadIdx.x & 31;
    if (warp >= TT) return;
    const float* hr = h2 + (size_t)warp * HH;
    float hv[32];
#pragma unroll
    for (int i = 0; i < 32; i++) hv[i] = hr[lane + i * 32];
    float logits[EE];
#pragma unroll
    for (int e = 0; e < EE; e++) {
        const float* wr = gw + e * HH;
        float s = 0.f;
#pragma unroll
        for (int i = 0; i < 32; i++) s = fmaf(hv[i], wr[lane + i * 32], s);
#pragma unroll
        for (int off = 16; off >= 1; off >>= 1)
            s += __shfl_xor_sync(0xffffffffu, s, off);
        logits[e] = s;
    }
    if (lane == 0) {
        int i0 = 0; float v0 = logits[0];
#pragma unroll
        for (int e = 1; e < EE; e++)
            if (logits[e] > v0) { v0 = logits[e]; i0 = e; }
        int i1 = -1; float v1 = -1e30f;
#pragma unroll
        for (int e = 0; e < EE; e++)
            if (e != i0 && logits[e] > v1) { v1 = logits[e]; i1 = e; }
        float r = __expf(v1 - v0);
        float z = 1.f + r;
        float w0 = 1.f / z, w1 = r / z;
        int p0 = atomicAdd(&g_cnt[i0], 1);
        g_tok[i0 * CAP + p0] = warp; g_coef[i0 * CAP + p0] = w0;
        int p1 = atomicAdd(&g_cnt[i1], 1);
        g_tok[i1 * CAP + p1] = warp; g_coef[i1 * CAP + p1] = w1;
    }
}

// ---------------- GLU ----------------
__global__ void glu_k() {
    int idx = blockIdx.x * blockDim.x + threadIdx.x;
    if (idx >= TT * SHD) return;
    int t = idx >> 10;
    int i = idx & 1023;
    float g = g_gu[(size_t)t * (2 * SHD) + i];
    float u = g_gu[(size_t)t * (2 * SHD) + SHD + i];
    g_act[idx] = g / (1.f + __expf(-g)) * u;
}

// ---------------- launch ----------------
extern "C" void kernel_launch(void* const* d_in, const int* in_sizes, int n_in,
                              void* d_out, int out_size) {
    const float* x   = (const float*)d_in[0];
    const float* ln1 = (const float*)d_in[2];
    const float* ln2 = (const float*)d_in[3];
    const float* Wq  = (const float*)d_in[4];
    const float* Wkv = (const float*)d_in[5];
    const float* Wo  = (const float*)d_in[6];
    const float* gw  = (const float*)d_in[7];
    const float* w1  = (const float*)d_in[8];
    const float* w2  = (const float*)d_in[9];
    const float* sgu = (const float*)d_in[10];
    const float* sdn = (const float*)d_in[11];
    float* out = (float*)d_out;

    void *p_hnorm, *p_qfull, *p_kv, *p_attn, *p_x1, *p_h2, *p_gu, *p_act;
    cudaGetSymbolAddress(&p_hnorm, g_hnorm);
    cudaGetSymbolAddress(&p_qfull, g_qfull);
    cudaGetSymbolAddress(&p_kv,    g_kv);
    cudaGetSymbolAddress(&p_attn,  g_attn);
    cudaGetSymbolAddress(&p_x1,    g_x1);
    cudaGetSymbolAddress(&p_h2,    g_h2);
    cudaGetSymbolAddress(&p_gu,    g_gu);
    cudaGetSymbolAddress(&p_act,   g_act);

    const int GEMM_SMEM = 3 * GTILE * 4 * 2;   // 61440 B
    static bool s_attr = false;
    if (!s_attr) {
        s_attr = true;
        cudaFuncSetAttribute(mma_gemm_k<0>, cudaFuncAttributeMaxDynamicSharedMemorySize, GEMM_SMEM);
        cudaFuncSetAttribute(mma_gemm_k<1>, cudaFuncAttributeMaxDynamicSharedMemorySize, GEMM_SMEM);
        cudaFuncSetAttribute(mma_gemm_k<2>, cudaFuncAttributeMaxDynamicSharedMemorySize, GEMM_SMEM);
        cudaFuncSetAttribute(mma_gemm_k<3>, cudaFuncAttributeMaxDynamicSharedMemorySize, GEMM_SMEM);
        cudaFuncSetAttribute(flashmma_k, cudaFuncAttributeMaxDynamicSharedMemorySize, FL_SMEM);
    }

    // attention block
    rmsnorm_k<<<TT, 256>>>(x, ln1, (float*)p_hnorm);
    mma_gemm_k<0><<<dim3(QCOLS / 128, TT / 128), 256, GEMM_SMEM>>>(
        (const float*)p_hnorm, Wq, (float*)p_qfull, QCOLS, nullptr, 0);
    mma_gemm_k<0><<<dim3(KVC / 128, TT / 128), 256, GEMM_SMEM>>>(
        (const float*)p_hnorm, Wkv, (float*)p_kv, KVC, nullptr, 0);
    flashmma_k<<<dim3(SS / 64, NHD, BB), 128, FL_SMEM>>>(
        (const float*)p_qfull, (const float*)p_kv, (float*)p_attn);
    mma_gemm_k<1><<<dim3(HH / 128, TT / 128), 256, GEMM_SMEM>>>(
        (const float*)p_attn, Wo, (float*)p_x1, HH, x, 0);

    // MoE block
    rmsnorm_k<<<TT, 256>>>((const float*)p_x1, ln2, (float*)p_h2);
    zero_cnt_k<<<1, 32>>>();
    gate_k<<<TT / 8, 256>>>((const float*)p_h2, gw);
    mma_gemm_k<0><<<dim3((2 * SHD) / 128, TT / 128), 256, GEMM_SMEM>>>(
        (const float*)p_h2, sgu, (float*)p_gu, 2 * SHD, nullptr, 0);
    glu_k<<<(TT * SHD) / 256, 256>>>();
    mma_gemm_k<1><<<dim3(HH / 128, TT / 128), 256, GEMM_SMEM>>>(
        (const float*)p_act, sdn, out, HH, (const float*)p_x1, 0);
    mma_gemm_k<2><<<dim3(INTER / 128, CAP / 128, EE), 256, GEMM_SMEM>>>(
        (const float*)p_h2, w1, nullptr, INTER, nullptr, (size_t)INTER * HH);
    mma_gemm_k<3><<<dim3(HH / 128, CAP / 128, EE), 256, GEMM_SMEM>>>(
        nullptr, w2, out, HH, nullptr, (size_t)HH * INTER);
}